// round 12
// baseline (speedup 1.0000x reference)
#include <cuda_runtime.h>
#include <cuda_bf16.h>
#include <cstdint>

// Shapes (fixed)
#define N_    4096
#define M_    128
#define Q_    64
#define D_    128
#define MQ_   8192
#define KSP   256            // stored split: [hi(2 chunks) | lo(2 chunks)], 64 elems/chunk
#define L2E   1.4426950408889634f

// ---------------- device scratch (static, allowed) -------------------------
__device__ float g_ca[N_];                            // pre-scaled by log2e
__device__ float g_cb[MQ_];                           // pre-scaled by log2e
__device__ __nv_bfloat16 g_Acat[(size_t)N_ * KSP];    // [hiA | loA]
__device__ __nv_bfloat16 g_Bcat[(size_t)MQ_ * KSP];   // [hiB | loB]

#define SWZ(x) ((x) ^ (((x) >> 3) & 0x70))

__device__ __forceinline__ uint32_t smem_u32(const void* p) {
    uint32_t a;
    asm("{ .reg .u64 t; cvta.to.shared.u64 t, %1; cvt.u32.u64 %0, t; }"
        : "=r"(a) : "l"(p));
    return a;
}

#define CP_ASYNC16(dst, src) \
    asm volatile("cp.async.cg.shared.global [%0], [%1], 16;" \
                 :: "r"(dst), "l"(src))
#define CP_COMMIT() asm volatile("cp.async.commit_group;" ::: "memory")

#define LDSM4(r0, r1, r2, r3, addr) \
    asm volatile("ldmatrix.sync.aligned.m8n8.x4.shared.b16 {%0,%1,%2,%3}, [%4];" \
                 : "=r"(r0), "=r"(r1), "=r"(r2), "=r"(r3) : "r"(addr))

#define MMA16816(cc, aa, b0, b1) \
    asm volatile("mma.sync.aligned.m16n8k16.row.col.f32.bf16.bf16.f32 " \
                 "{%0,%1,%2,%3}, {%4,%5,%6,%7}, {%8,%9}, {%0,%1,%2,%3};" \
                 : "+f"((cc)[0]), "+f"((cc)[1]), "+f"((cc)[2]), "+f"((cc)[3]) \
                 : "r"((aa)[0]), "r"((aa)[1]), "r"((aa)[2]), "r"((aa)[3]), \
                   "r"(b0), "r"(b1))

__device__ __forceinline__ float ex2(float x) {
    float r;
    asm("ex2.approx.f32 %0, %1;" : "=f"(r) : "f"(x));
    return r;
}

// ---------------- prep: norms (pre-scaled by log2e) + hi/lo bf16 split -----
// Half-warp per row, 2 rows per warp (2 independent loads per thread).
__global__ __launch_bounds__(256) void kde_prep(const float* __restrict__ a,
                                                const float* __restrict__ b,
                                                const float* __restrict__ var) {
    int warp  = (blockIdx.x * blockDim.x + threadIdx.x) >> 5;
    int lane  = threadIdx.x & 31;
    int half  = lane >> 4;          // which of 2 rows this half-warp owns
    int l16   = lane & 15;
    int row   = warp * 2 + half;
    if (row >= N_ + MQ_) return;
    bool isA = row < N_;
    const float* src = isA ? (a + (size_t)row * D_)
                           : (b + (size_t)(row - N_) * D_);
    // two float4 per thread: elements [4*l16 .. +3] and [4*(l16+16) .. +3]
    float4 v0 = reinterpret_cast<const float4*>(src)[l16];
    float4 v1 = reinterpret_cast<const float4*>(src)[l16 + 16];
    float s = v0.x * v0.x + v0.y * v0.y + v0.z * v0.z + v0.w * v0.w
            + v1.x * v1.x + v1.y * v1.y + v1.z * v1.z + v1.w * v1.w;
    #pragma unroll
    for (int o = 8; o; o >>= 1) s += __shfl_xor_sync(0xffffffffu, s, o);
    if (l16 == 0) {
        float c = -0.5f * (1.0f / var[0]) * s * L2E;
        if (isA) g_ca[row] = c; else g_cb[row - N_] = c;
    }
    __nv_bfloat16* base = isA ? (g_Acat + (size_t)row * KSP)
                              : (g_Bcat + (size_t)(row - N_) * KSP);
    float f[8] = {v0.x, v0.y, v0.z, v0.w, v1.x, v1.y, v1.z, v1.w};
    union { unsigned long long u; __nv_bfloat16 h[4]; } HP[2], LP[2];
    #pragma unroll
    for (int g = 0; g < 2; g++)
        #pragma unroll
        for (int i = 0; i < 4; i++) {
            __nv_bfloat16 h = __float2bfloat16(f[g * 4 + i]);
            HP[g].h[i] = h;
            LP[g].h[i] = __float2bfloat16(f[g * 4 + i] - __bfloat162float(h));
        }
    *(unsigned long long*)(base + 4 * l16)              = HP[0].u;  // hi part 1
    *(unsigned long long*)(base + 4 * (l16 + 16))       = HP[1].u;  // hi part 2
    *(unsigned long long*)(base + 128 + 4 * l16)        = LP[0].u;  // lo part 1
    *(unsigned long long*)(base + 128 + 4 * (l16 + 16)) = LP[1].u;  // lo part 2
}

// ---------------- main: warp-MMA GEMM + fused exp/Q-sum --------------------
// CTA tile 128(n) x 128(mq). A fully resident in smem (all 4 K-chunks, 64KB,
// staged once). B streamed through a 3-buffer ring; each of the 4 B chunks
// staged once. Compute order (Achunk, Bchunk):
//   (0,b0)(2,b0)(1,b1)(3,b1)(0,b2)(1,b3)  == hi.hi + lo.hi + hi.lo
#define OFF_A   0
#define OFF_B   65536
#define OFF_CB  (OFF_B + 3 * 16384)
#define SMEM_USE (OFF_CB + 512)
#define SMEM_TOTAL (SMEM_USE + 1024)   // alignment slack

__global__ __launch_bounds__(128, 2) void kde_main(const float* __restrict__ var,
                                                   float* __restrict__ dens) {
    extern __shared__ char smem_raw[];
    uint32_t sb_raw = smem_u32(smem_raw);
    uint32_t sb = (sb_raw + 1023) & ~1023u;
    char* smem = smem_raw + (sb - sb_raw);

    const int tid  = threadIdx.x;
    const int lane = tid & 31;
    const int wid  = tid >> 5;
    const int wm   = wid & 1;     // 2 warps along n-rows (64 each)
    const int wn   = wid >> 1;    // 2 warps along mq-cols (64 each)

    ((float*)(smem + OFF_CB))[tid] = g_cb[blockIdx.y * 128 + tid];

    const __nv_bfloat16* Abase = g_Acat + (size_t)(blockIdx.x * 128) * KSP;
    const __nv_bfloat16* Bbase = g_Bcat + (size_t)(blockIdx.y * 128) * KSP;

    float acc[4][8][4];
    #pragma unroll
    for (int t = 0; t < 4; t++)
        #pragma unroll
        for (int nt = 0; nt < 8; nt++)
            #pragma unroll
            for (int r = 0; r < 4; r++) acc[t][nt][r] = 0.0f;

    // ---- stage ALL of A (4 chunks x 16KB) as one group --------------------
    auto stage_A = [&]() {
        #pragma unroll
        for (int ac = 0; ac < 4; ac++) {
            uint32_t dst = sb + OFF_A + ac * 16384;
            #pragma unroll
            for (int j = 0; j < 8; j++) {
                int idx = tid + j * 128;
                int row = idx >> 3, col = idx & 7;
                const void* src = Abase + (size_t)row * KSP + ac * 64 + col * 8;
                CP_ASYNC16(dst + SWZ((uint32_t)(row * 128 + col * 16)), src);
            }
        }
        CP_COMMIT();
    };

    // ---- stage one B chunk into ring buffer -------------------------------
    auto stage_B = [&](int bc, int ring) {
        uint32_t dst = sb + OFF_B + ring * 16384;
        #pragma unroll
        for (int j = 0; j < 8; j++) {
            int idx = tid + j * 128;
            int row = idx >> 3, col = idx & 7;
            const void* src = Bbase + (size_t)row * KSP + bc * 64 + col * 8;
            CP_ASYNC16(dst + SWZ((uint32_t)(row * 128 + col * 16)), src);
        }
        CP_COMMIT();
    };

    // ---- compute one (Achunk, Bring) pair ---------------------------------
    auto compute = [&](int ac, int ring) {
        uint32_t abase = sb + OFF_A + ac * 16384;
        uint32_t bbase = sb + OFF_B + ring * 16384;
        #pragma unroll
        for (int ks = 0; ks < 4; ks++) {
            uint32_t af[4][4];
            #pragma unroll
            for (int t = 0; t < 4; t++) {
                int row  = wm * 64 + t * 16 + (lane & 7) + ((lane & 8) ? 8 : 0);
                int colb = ks * 32 + ((lane & 16) ? 16 : 0);
                LDSM4(af[t][0], af[t][1], af[t][2], af[t][3],
                      abase + SWZ((uint32_t)(row * 128 + colb)));
            }
            uint32_t bf[8][2];
            #pragma unroll
            for (int p = 0; p < 4; p++) {
                int row  = wn * 64 + p * 16 + (lane & 7) + ((lane & 16) ? 8 : 0);
                int colb = ks * 32 + ((lane & 8) ? 16 : 0);
                LDSM4(bf[2 * p][0], bf[2 * p][1], bf[2 * p + 1][0], bf[2 * p + 1][1],
                      bbase + SWZ((uint32_t)(row * 128 + colb)));
            }
            #pragma unroll
            for (int t = 0; t < 4; t++)
                #pragma unroll
                for (int nt = 0; nt < 8; nt++)
                    MMA16816(acc[t][nt], af[t], bf[nt][0], bf[nt][1]);
        }
    };

    // ---- schedule ---------------------------------------------------------
    stage_A();           // g0
    stage_B(0, 0);       // g1
    stage_B(1, 1);       // g2
    stage_B(2, 2);       // g3

    asm volatile("cp.async.wait_group 2;" ::: "memory");   // g0,g1 done
    __syncthreads();
    compute(0, 0);       // hiA0 . hiB0
    compute(2, 0);       // loA0 . hiB0

    asm volatile("cp.async.wait_group 1;" ::: "memory");   // g2 done
    __syncthreads();     // ring0 dead; b1 visible
    stage_B(3, 0);       // g4
    compute(1, 1);       // hiA1 . hiB1
    compute(3, 1);       // loA1 . hiB1

    asm volatile("cp.async.wait_group 1;" ::: "memory");   // g3 done
    __syncthreads();
    compute(0, 2);       // hiA0 . loB0

    asm volatile("cp.async.wait_group 0;" ::: "memory");   // g4 done
    __syncthreads();
    compute(1, 0);       // hiA1 . loB1

    // ---- epilogue: ex2 + Q-sum (warp's 64 cols == one m-cluster) ----------
    const float ivl = (1.0f / var[0]) * L2E;
    const float* cbp = (const float*)(smem + OFF_CB);
    const int mcl = blockIdx.y * 2 + wn;

    #pragma unroll
    for (int t = 0; t < 4; t++) {
        #pragma unroll
        for (int h = 0; h < 2; h++) {
            int row = blockIdx.x * 128 + wm * 64 + t * 16 + h * 8 + (lane >> 2);
            float ca = g_ca[row];
            float s = 0.0f;
            #pragma unroll
            for (int nt = 0; nt < 8; nt++) {
                int ncol = wn * 64 + nt * 8 + (lane & 3) * 2;
                s += ex2(fmaf(acc[t][nt][h * 2 + 0], ivl, ca + cbp[ncol]));
                s += ex2(fmaf(acc[t][nt][h * 2 + 1], ivl, ca + cbp[ncol + 1]));
            }
            s += __shfl_xor_sync(0xffffffffu, s, 1);
            s += __shfl_xor_sync(0xffffffffu, s, 2);
            if ((lane & 3) == 0) dens[(size_t)row * M_ + mcl] = s;
        }
    }
}

// ---------------- normalize rows -------------------------------------------
__global__ __launch_bounds__(256) void kde_norm(float* __restrict__ out) {
    int warp = (blockIdx.x * blockDim.x + threadIdx.x) >> 5;
    int lane = threadIdx.x & 31;
    if (warp >= N_) return;
    float4* row = reinterpret_cast<float4*>(out + (size_t)warp * M_);
    float4 v = row[lane];
    float s = v.x + v.y + v.z + v.w;
    #pragma unroll
    for (int o = 16; o; o >>= 1) s += __shfl_xor_sync(0xffffffffu, s, o);
    float inv = 1.0f / (s + 1e-10f);
    v.x *= inv; v.y *= inv; v.z *= inv; v.w *= inv;
    row[lane] = v;
}

// ---------------------------------------------------------------------------
extern "C" void kernel_launch(void* const* d_in, const int* in_sizes, int n_in,
                              void* d_out, int out_size) {
    const float* a   = (const float*)d_in[0];   // [4096,128]
    const float* b   = (const float*)d_in[1];   // [128,64,128]
    const float* var = (const float*)d_in[2];   // [1]
    float* out = (float*)d_out;                 // [4096,128]

    cudaFuncSetAttribute(kde_main, cudaFuncAttributeMaxDynamicSharedMemorySize,
                         SMEM_TOTAL);

    // 12288 rows, 2 rows per warp, 8 warps per block -> 16 rows per block
    kde_prep<<<(N_ + MQ_) / 16, 256>>>(a, b, var);
    kde_main<<<dim3(N_ / 128, MQ_ / 128), 128, SMEM_TOTAL>>>(var, out);
    kde_norm<<<N_ / 8, 256>>>(out);
}

// round 16
// speedup vs baseline: 1.4655x; 1.4655x over previous
#include <cuda_runtime.h>
#include <cuda_bf16.h>
#include <cstdint>

// Shapes (fixed)
#define N_    4096
#define M_    128
#define Q_    64
#define D_    128
#define MQ_   8192
#define KSP   256            // stored split: [hi(2 chunks) | lo(2 chunks)], 64 elems/chunk
#define L2E   1.4426950408889634f

// ---------------- device scratch (static, allowed) -------------------------
__device__ float g_ca[N_];                            // pre-scaled by log2e
__device__ float g_cb[MQ_];                           // pre-scaled by log2e
__device__ __nv_bfloat16 g_Acat[(size_t)N_ * KSP];    // [hiA | loA]
__device__ __nv_bfloat16 g_Bcat[(size_t)MQ_ * KSP];   // [hiB | loB]

#define SWZ(x) ((x) ^ (((x) >> 3) & 0x70))

__device__ __forceinline__ uint32_t smem_u32(const void* p) {
    uint32_t a;
    asm("{ .reg .u64 t; cvta.to.shared.u64 t, %1; cvt.u32.u64 %0, t; }"
        : "=r"(a) : "l"(p));
    return a;
}

#define CP_ASYNC16(dst, src) \
    asm volatile("cp.async.cg.shared.global [%0], [%1], 16;" \
                 :: "r"(dst), "l"(src))
#define CP_COMMIT() asm volatile("cp.async.commit_group;" ::: "memory")

#define LDSM4(r0, r1, r2, r3, addr) \
    asm volatile("ldmatrix.sync.aligned.m8n8.x4.shared.b16 {%0,%1,%2,%3}, [%4];" \
                 : "=r"(r0), "=r"(r1), "=r"(r2), "=r"(r3) : "r"(addr))

#define MMA16816(cc, aa, b0, b1) \
    asm volatile("mma.sync.aligned.m16n8k16.row.col.f32.bf16.bf16.f32 " \
                 "{%0,%1,%2,%3}, {%4,%5,%6,%7}, {%8,%9}, {%0,%1,%2,%3};" \
                 : "+f"((cc)[0]), "+f"((cc)[1]), "+f"((cc)[2]), "+f"((cc)[3]) \
                 : "r"((aa)[0]), "r"((aa)[1]), "r"((aa)[2]), "r"((aa)[3]), \
                   "r"(b0), "r"(b1))

__device__ __forceinline__ float ex2(float x) {
    float r;
    asm("ex2.approx.f32 %0, %1;" : "=f"(r) : "f"(x));
    return r;
}

// ---------------- prep: norms (pre-scaled by log2e) + hi/lo bf16 split -----
__global__ __launch_bounds__(256) void kde_prep(const float* __restrict__ a,
                                                const float* __restrict__ b,
                                                const float* __restrict__ var) {
    int warp  = (blockIdx.x * blockDim.x + threadIdx.x) >> 5;
    int lane  = threadIdx.x & 31;
    int half  = lane >> 4;          // which of 2 rows this half-warp owns
    int l16   = lane & 15;
    int row   = warp * 2 + half;
    if (row >= N_ + MQ_) return;
    bool isA = row < N_;
    const float* src = isA ? (a + (size_t)row * D_)
                           : (b + (size_t)(row - N_) * D_);
    float4 v0 = reinterpret_cast<const float4*>(src)[l16];
    float4 v1 = reinterpret_cast<const float4*>(src)[l16 + 16];
    float s = v0.x * v0.x + v0.y * v0.y + v0.z * v0.z + v0.w * v0.w
            + v1.x * v1.x + v1.y * v1.y + v1.z * v1.z + v1.w * v1.w;
    #pragma unroll
    for (int o = 8; o; o >>= 1) s += __shfl_xor_sync(0xffffffffu, s, o);
    if (l16 == 0) {
        float c = -0.5f * (1.0f / var[0]) * s * L2E;
        if (isA) g_ca[row] = c; else g_cb[row - N_] = c;
    }
    __nv_bfloat16* base = isA ? (g_Acat + (size_t)row * KSP)
                              : (g_Bcat + (size_t)(row - N_) * KSP);
    float f[8] = {v0.x, v0.y, v0.z, v0.w, v1.x, v1.y, v1.z, v1.w};
    union { unsigned long long u; __nv_bfloat16 h[4]; } HP[2], LP[2];
    #pragma unroll
    for (int g = 0; g < 2; g++)
        #pragma unroll
        for (int i = 0; i < 4; i++) {
            __nv_bfloat16 h = __float2bfloat16(f[g * 4 + i]);
            HP[g].h[i] = h;
            LP[g].h[i] = __float2bfloat16(f[g * 4 + i] - __bfloat162float(h));
        }
    *(unsigned long long*)(base + 4 * l16)              = HP[0].u;
    *(unsigned long long*)(base + 4 * (l16 + 16))       = HP[1].u;
    *(unsigned long long*)(base + 128 + 4 * l16)        = LP[0].u;
    *(unsigned long long*)(base + 128 + 4 * (l16 + 16)) = LP[1].u;
}

// ---------------- main: warp-MMA GEMM + fused exp/Q-sum --------------------
// CTA tile 128(n) x 128(mq). A fully resident (4 chunks, 64KB, staged once).
// B streamed through a TWO-buffer ring (32KB) so smem = 96.5KB -> 2 CTA/SM.
// Compute order (Achunk, Bchunk):
//   (0,b0)(2,b0) | (1,b1)(3,b1) | (0,b2) | (1,b3)  == hi.hi + lo.hi + hi.lo
#define OFF_A   0
#define OFF_B   65536
#define OFF_CB  (OFF_B + 2 * 16384)
#define SMEM_USE (OFF_CB + 512)
#define SMEM_TOTAL (SMEM_USE + 1024)   // alignment slack

__global__ __launch_bounds__(128, 2) void kde_main(const float* __restrict__ var,
                                                   float* __restrict__ dens) {
    extern __shared__ char smem_raw[];
    uint32_t sb_raw = smem_u32(smem_raw);
    uint32_t sb = (sb_raw + 1023) & ~1023u;
    char* smem = smem_raw + (sb - sb_raw);

    const int tid  = threadIdx.x;
    const int lane = tid & 31;
    const int wid  = tid >> 5;
    const int wm   = wid & 1;     // 2 warps along n-rows (64 each)
    const int wn   = wid >> 1;    // 2 warps along mq-cols (64 each)

    ((float*)(smem + OFF_CB))[tid] = g_cb[blockIdx.y * 128 + tid];

    const __nv_bfloat16* Abase = g_Acat + (size_t)(blockIdx.x * 128) * KSP;
    const __nv_bfloat16* Bbase = g_Bcat + (size_t)(blockIdx.y * 128) * KSP;

    float acc[4][8][4];
    #pragma unroll
    for (int t = 0; t < 4; t++)
        #pragma unroll
        for (int nt = 0; nt < 8; nt++)
            #pragma unroll
            for (int r = 0; r < 4; r++) acc[t][nt][r] = 0.0f;

    // ---- stage ALL of A (4 chunks x 16KB) as one group --------------------
    auto stage_A = [&]() {
        #pragma unroll
        for (int ac = 0; ac < 4; ac++) {
            uint32_t dst = sb + OFF_A + ac * 16384;
            #pragma unroll
            for (int j = 0; j < 8; j++) {
                int idx = tid + j * 128;
                int row = idx >> 3, col = idx & 7;
                const void* src = Abase + (size_t)row * KSP + ac * 64 + col * 8;
                CP_ASYNC16(dst + SWZ((uint32_t)(row * 128 + col * 16)), src);
            }
        }
        CP_COMMIT();
    };

    // ---- stage one B chunk into ring buffer -------------------------------
    auto stage_B = [&](int bc, int ring) {
        uint32_t dst = sb + OFF_B + ring * 16384;
        #pragma unroll
        for (int j = 0; j < 8; j++) {
            int idx = tid + j * 128;
            int row = idx >> 3, col = idx & 7;
            const void* src = Bbase + (size_t)row * KSP + bc * 64 + col * 8;
            CP_ASYNC16(dst + SWZ((uint32_t)(row * 128 + col * 16)), src);
        }
        CP_COMMIT();
    };

    // ---- compute one (Achunk, Bring) pair ---------------------------------
    auto compute = [&](int ac, int ring) {
        uint32_t abase = sb + OFF_A + ac * 16384;
        uint32_t bbase = sb + OFF_B + ring * 16384;
        #pragma unroll
        for (int ks = 0; ks < 4; ks++) {
            uint32_t af[4][4];
            #pragma unroll
            for (int t = 0; t < 4; t++) {
                int row  = wm * 64 + t * 16 + (lane & 7) + ((lane & 8) ? 8 : 0);
                int colb = ks * 32 + ((lane & 16) ? 16 : 0);
                LDSM4(af[t][0], af[t][1], af[t][2], af[t][3],
                      abase + SWZ((uint32_t)(row * 128 + colb)));
            }
            uint32_t bf[8][2];
            #pragma unroll
            for (int p = 0; p < 4; p++) {
                int row  = wn * 64 + p * 16 + (lane & 7) + ((lane & 16) ? 8 : 0);
                int colb = ks * 32 + ((lane & 8) ? 16 : 0);
                LDSM4(bf[2 * p][0], bf[2 * p][1], bf[2 * p + 1][0], bf[2 * p + 1][1],
                      bbase + SWZ((uint32_t)(row * 128 + colb)));
            }
            #pragma unroll
            for (int t = 0; t < 4; t++)
                #pragma unroll
                for (int nt = 0; nt < 8; nt++)
                    MMA16816(acc[t][nt], af[t], bf[nt][0], bf[nt][1]);
        }
    };

    // ---- schedule (2-buffer B ring, each B chunk staged once) -------------
    stage_A();           // g0
    stage_B(0, 0);       // g1
    stage_B(1, 1);       // g2

    asm volatile("cp.async.wait_group 1;" ::: "memory");   // g0,g1 done
    __syncthreads();
    compute(0, 0);       // hiA0 . hiB0
    compute(2, 0);       // loA0 . hiB0
    __syncthreads();     // ring0 free

    stage_B(2, 0);       // g3
    asm volatile("cp.async.wait_group 1;" ::: "memory");   // g2 done
    __syncthreads();
    compute(1, 1);       // hiA1 . hiB1
    compute(3, 1);       // loA1 . hiB1
    __syncthreads();     // ring1 free

    stage_B(3, 1);       // g4
    asm volatile("cp.async.wait_group 1;" ::: "memory");   // g3 done
    __syncthreads();
    compute(0, 0);       // hiA0 . loB0

    asm volatile("cp.async.wait_group 0;" ::: "memory");   // g4 done
    __syncthreads();
    compute(1, 1);       // hiA1 . loB1

    // ---- epilogue: ex2 + Q-sum (warp's 64 cols == one m-cluster) ----------
    const float ivl = (1.0f / var[0]) * L2E;
    const float* cbp = (const float*)(smem + OFF_CB);
    const int mcl = blockIdx.y * 2 + wn;

    #pragma unroll
    for (int t = 0; t < 4; t++) {
        #pragma unroll
        for (int h = 0; h < 2; h++) {
            int row = blockIdx.x * 128 + wm * 64 + t * 16 + h * 8 + (lane >> 2);
            float ca = g_ca[row];
            float s = 0.0f;
            #pragma unroll
            for (int nt = 0; nt < 8; nt++) {
                int ncol = wn * 64 + nt * 8 + (lane & 3) * 2;
                s += ex2(fmaf(acc[t][nt][h * 2 + 0], ivl, ca + cbp[ncol]));
                s += ex2(fmaf(acc[t][nt][h * 2 + 1], ivl, ca + cbp[ncol + 1]));
            }
            s += __shfl_xor_sync(0xffffffffu, s, 1);
            s += __shfl_xor_sync(0xffffffffu, s, 2);
            if ((lane & 3) == 0) dens[(size_t)row * M_ + mcl] = s;
        }
    }
}

// ---------------- normalize rows -------------------------------------------
__global__ __launch_bounds__(256) void kde_norm(float* __restrict__ out) {
    int warp = (blockIdx.x * blockDim.x + threadIdx.x) >> 5;
    int lane = threadIdx.x & 31;
    if (warp >= N_) return;
    float4* row = reinterpret_cast<float4*>(out + (size_t)warp * M_);
    float4 v = row[lane];
    float s = v.x + v.y + v.z + v.w;
    #pragma unroll
    for (int o = 16; o; o >>= 1) s += __shfl_xor_sync(0xffffffffu, s, o);
    float inv = 1.0f / (s + 1e-10f);
    v.x *= inv; v.y *= inv; v.z *= inv; v.w *= inv;
    row[lane] = v;
}

// ---------------------------------------------------------------------------
extern "C" void kernel_launch(void* const* d_in, const int* in_sizes, int n_in,
                              void* d_out, int out_size) {
    const float* a   = (const float*)d_in[0];   // [4096,128]
    const float* b   = (const float*)d_in[1];   // [128,64,128]
    const float* var = (const float*)d_in[2];   // [1]
    float* out = (float*)d_out;                 // [4096,128]

    cudaFuncSetAttribute(kde_main, cudaFuncAttributeMaxDynamicSharedMemorySize,
                         SMEM_TOTAL);

    kde_prep<<<(N_ + MQ_) / 16, 256>>>(a, b, var);
    kde_main<<<dim3(N_ / 128, MQ_ / 128), 128, SMEM_TOTAL>>>(var, out);
    kde_norm<<<N_ / 8, 256>>>(out);
}